// round 3
// baseline (speedup 1.0000x reference)
#include <cuda_runtime.h>
#include <cstdint>

#define NN   50000
#define EMBD 256
#define NE   800000
#define ETOT (NE + NN)

// ---------------- static device scratch (no allocations allowed) ----------------
__device__ float g_h[(size_t)NN * EMBD];      // GEMM output (per-layer features)
__device__ float g_o1[(size_t)NN * EMBD];     // layer-1 aggregated output
__device__ float g_als[NN * 8];
__device__ float g_ald[NN * 8];
__device__ float g_alpha[(size_t)ETOT * 8];   // per-edge per-head attention
__device__ int   g_rowptr[NN + 1];
__device__ int   g_cnt[NN];
__device__ int   g_srcs[ETOT];
__device__ int   g_is64;                      // edge_index dtype flag (1 = int64, 0 = int32)

__device__ __forceinline__ float lrelu(float x) { return x > 0.f ? x : 0.2f * x; }

__device__ __forceinline__ int edge_at(const void* ei, long long idx) {
    if (g_is64) return (int)((const long long*)ei)[idx];
    return ((const int*)ei)[idx];
}

// ---------------- dtype probe: reads only first 64 bytes (safe either way) ----------------
__global__ void detect_kernel(const void* ei) {
    const long long* p = (const long long*)ei;
    bool ok = true;
    #pragma unroll
    for (int i = 0; i < 8; i++) {
        long long v = p[i];
        if (v < 0 || v >= NN) ok = false;
    }
    g_is64 = ok ? 1 : 0;
}

// ---------------- CSR build ----------------
__global__ void zero_cnt_kernel() {
    int i = blockIdx.x * blockDim.x + threadIdx.x;
    if (i < NN) g_cnt[i] = 0;
}

__global__ void deg_kernel(const void* __restrict__ ei) {
    int e = blockIdx.x * blockDim.x + threadIdx.x;
    if (e < NE) {
        int d = edge_at(ei, (long long)NE + e);
        atomicAdd(&g_cnt[d], 1);
    }
}

// single-block exclusive scan of (cnt[i] + 1)  ->  rowptr ; also zeroes cnt (cursor reuse)
__global__ void scan_kernel() {
    __shared__ int warp_sums[32];
    __shared__ int s_running;
    const int t = threadIdx.x;
    if (t == 0) { s_running = 0; g_rowptr[0] = 0; }
    __syncthreads();
    for (int base = 0; base < NN; base += 1024) {
        int i = base + t;
        int v = 0;
        if (i < NN) { v = g_cnt[i] + 1; g_cnt[i] = 0; }
        int x = v;
        #pragma unroll
        for (int o = 1; o < 32; o <<= 1) {
            int y = __shfl_up_sync(0xffffffffu, x, o);
            if ((t & 31) >= o) x += y;
        }
        if ((t & 31) == 31) warp_sums[t >> 5] = x;
        __syncthreads();
        if (t < 32) {
            int w = warp_sums[t];
            #pragma unroll
            for (int o = 1; o < 32; o <<= 1) {
                int y = __shfl_up_sync(0xffffffffu, w, o);
                if (t >= o) w += y;
            }
            warp_sums[t] = w;
        }
        __syncthreads();
        int prefix = (t >= 32) ? warp_sums[(t >> 5) - 1] : 0;
        int incl = x + prefix + s_running;
        if (i < NN) g_rowptr[i + 1] = incl;
        __syncthreads();
        if (t == 1023) s_running = incl;
        __syncthreads();
    }
}

__global__ void scatter_kernel(const void* __restrict__ ei) {
    int e = blockIdx.x * blockDim.x + threadIdx.x;
    if (e < NE) {
        int s = edge_at(ei, e);
        int d = edge_at(ei, (long long)NE + e);
        int pos = g_rowptr[d] + atomicAdd(&g_cnt[d], 1);
        g_srcs[pos] = s;
    }
}

__global__ void self_kernel() {
    int i = blockIdx.x * blockDim.x + threadIdx.x;
    if (i < NN) g_srcs[g_rowptr[i + 1] - 1] = i;
}

// ---------------- GEMM:  g_h[M,256] = A[M,256] @ B[256,256]  (fp32 SIMT, 128x128 tile) ----
// INTERNAL_SRC: A comes from g_o1 (layer 2); otherwise from the passed pointer (x).
template <bool INTERNAL_SRC>
__global__ void __launch_bounds__(256) gemm_kernel(const float* __restrict__ Aext,
                                                   const float* __restrict__ B, int M) {
    const float* A = INTERNAL_SRC ? g_o1 : Aext;
    float* C = g_h;
    __shared__ float As[8][128];
    __shared__ float Bs[8][128];
    const int t  = threadIdx.x;
    const int bm = blockIdx.x * 128;
    const int bn = blockIdx.y * 128;
    const int tr = t >> 4, tc = t & 15;
    const int arow = t >> 1;
    const int akk  = (t & 1) * 4;
    const int brow = t >> 5;
    const int bcol = (t & 31) * 4;
    const int gar = bm + arow;

    float acc[8][8];
    #pragma unroll
    for (int i = 0; i < 8; i++)
        #pragma unroll
        for (int j = 0; j < 8; j++) acc[i][j] = 0.f;

    float4 av = (gar < M) ? *(const float4*)(A + (size_t)gar * EMBD + akk)
                          : make_float4(0.f, 0.f, 0.f, 0.f);
    float4 bv = *(const float4*)(B + (size_t)brow * EMBD + bn + bcol);

    for (int k0 = 0; k0 < EMBD; k0 += 8) {
        As[akk + 0][arow] = av.x;
        As[akk + 1][arow] = av.y;
        As[akk + 2][arow] = av.z;
        As[akk + 3][arow] = av.w;
        *(float4*)&Bs[brow][bcol] = bv;
        __syncthreads();
        if (k0 + 8 < EMBD) {
            int k1 = k0 + 8;
            av = (gar < M) ? *(const float4*)(A + (size_t)gar * EMBD + k1 + akk)
                           : make_float4(0.f, 0.f, 0.f, 0.f);
            bv = *(const float4*)(B + (size_t)(brow + k1) * EMBD + bn + bcol);
        }
        #pragma unroll
        for (int kk = 0; kk < 8; kk++) {
            float ra[8], rb[8];
            *(float4*)&ra[0] = *(const float4*)&As[kk][tr * 8];
            *(float4*)&ra[4] = *(const float4*)&As[kk][tr * 8 + 4];
            *(float4*)&rb[0] = *(const float4*)&Bs[kk][tc * 8];
            *(float4*)&rb[4] = *(const float4*)&Bs[kk][tc * 8 + 4];
            #pragma unroll
            for (int i = 0; i < 8; i++)
                #pragma unroll
                for (int j = 0; j < 8; j++) acc[i][j] += ra[i] * rb[j];
        }
        __syncthreads();
    }

    #pragma unroll
    for (int i = 0; i < 8; i++) {
        int row = bm + tr * 8 + i;
        if (row < M) {
            *(float4*)(C + (size_t)row * EMBD + bn + tc * 8)     = make_float4(acc[i][0], acc[i][1], acc[i][2], acc[i][3]);
            *(float4*)(C + (size_t)row * EMBD + bn + tc * 8 + 4) = make_float4(acc[i][4], acc[i][5], acc[i][6], acc[i][7]);
        }
    }
}

// ---------------- per-node attention logits al_s / al_d (reads g_h) ----------------
template <int H>
__global__ void al_kernel(const float* __restrict__ asrc,
                          const float* __restrict__ adst) {
    int n = blockIdx.x, t = threadIdx.x;
    float v  = g_h[(size_t)n * EMBD + t];
    float ps = v * asrc[t];
    float pd = v * adst[t];
    #pragma unroll
    for (int o = 16; o; o >>= 1) {
        ps += __shfl_xor_sync(0xffffffffu, ps, o);
        pd += __shfl_xor_sync(0xffffffffu, pd, o);
    }
    if (H == 8) {
        if ((t & 31) == 0) { g_als[n * 8 + (t >> 5)] = ps; g_ald[n * 8 + (t >> 5)] = pd; }
    } else {
        __shared__ float sps[8], spd[8];
        if ((t & 31) == 0) { sps[t >> 5] = ps; spd[t >> 5] = pd; }
        __syncthreads();
        if (t == 0) {
            float a = 0.f, b = 0.f;
            #pragma unroll
            for (int w = 0; w < 8; w++) { a += sps[w]; b += spd[w]; }
            g_als[n] = a; g_ald[n] = b;
        }
    }
}

// ---------------- segment softmax over incoming edges of each dst ----------------
template <int H>
__global__ void __launch_bounds__(256) softmax_kernel() {
    constexpr int CAP   = (H == 8) ? 512 : 4096;
    constexpr int GROUP = (H == 8) ? 32 : 256;
    __shared__ float lsh[H][CAP];
    __shared__ float red[8];

    const int d = blockIdx.x;
    const int begin = g_rowptr[d], end = g_rowptr[d + 1];
    const int deg = end - begin;
    const int hh   = (H == 8) ? (threadIdx.x >> 5) : 0;
    const int lane = (H == 8) ? (threadIdx.x & 31) : threadIdx.x;
    const float aldv = g_ald[d * H + hh];

    float m = -1e30f;
    for (int i = lane; i < deg; i += GROUP) {
        int s = g_srcs[begin + i];
        float lg = lrelu(g_als[s * H + hh] + aldv);
        if (i < CAP) lsh[hh][i] = lg;
        m = fmaxf(m, lg);
    }
    #pragma unroll
    for (int o = 16; o; o >>= 1) m = fmaxf(m, __shfl_xor_sync(0xffffffffu, m, o));
    if (H == 1) {
        if ((threadIdx.x & 31) == 0) red[threadIdx.x >> 5] = m;
        __syncthreads();
        m = red[0];
        #pragma unroll
        for (int w = 1; w < 8; w++) m = fmaxf(m, red[w]);
        __syncthreads();
    }

    float z = 0.f;
    for (int i = lane; i < deg; i += GROUP) {
        float lg = (i < CAP) ? lsh[hh][i]
                             : lrelu(g_als[g_srcs[begin + i] * H + hh] + aldv);
        z += __expf(lg - m);
    }
    #pragma unroll
    for (int o = 16; o; o >>= 1) z += __shfl_xor_sync(0xffffffffu, z, o);
    if (H == 1) {
        if ((threadIdx.x & 31) == 0) red[threadIdx.x >> 5] = z;
        __syncthreads();
        z = 0.f;
        #pragma unroll
        for (int w = 0; w < 8; w++) z += red[w];
    }

    const float inv = 1.f / (z + 1e-16f);
    for (int i = lane; i < deg; i += GROUP) {
        float lg = (i < CAP) ? lsh[hh][i]
                             : lrelu(g_als[g_srcs[begin + i] * H + hh] + aldv);
        g_alpha[(size_t)(begin + i) * H + hh] = __expf(lg - m) * inv;
    }
}

// ---------------- aggregation:  dst[d,:] = sum_e alpha[e,h] * g_h[src_e,:] + b ----------------
// INTERNAL_DST: write to g_o1 (layer 1); otherwise to the passed pointer (d_out).
template <int H, bool INTERNAL_DST>
__global__ void __launch_bounds__(256) agg_kernel(const float* __restrict__ bias,
                                                  float* __restrict__ outext) {
    constexpr int F = EMBD / H;
    const int d = blockIdx.x, t = threadIdx.x;
    const int hh = t / F;
    const int begin = g_rowptr[d], end = g_rowptr[d + 1];

    __shared__ int   s_src[64];
    __shared__ float s_alpha[64 * H];

    float acc = 0.f;
    for (int c = begin; c < end; c += 64) {
        int len = min(64, end - c);
        __syncthreads();
        if (t < len) s_src[t] = g_srcs[c + t];
        for (int i = t; i < len * H; i += 256) s_alpha[i] = g_alpha[(size_t)c * H + i];
        __syncthreads();
        #pragma unroll 4
        for (int j = 0; j < len; j++)
            acc += s_alpha[j * H + hh] * g_h[(size_t)s_src[j] * EMBD + t];
    }
    float r = acc + bias[t];
    if (INTERNAL_DST) g_o1[(size_t)d * EMBD + t] = r;
    else              outext[(size_t)d * EMBD + t] = r;
}

// ---------------- launch (kernel launches ONLY — graph-capturable) ----------------
extern "C" void kernel_launch(void* const* d_in, const int* in_sizes, int n_in,
                              void* d_out, int out_size) {
    const float* x   = (const float*)d_in[0];
    const void*  ei  = d_in[1];
    const float* W1  = (const float*)d_in[2];
    const float* as1 = (const float*)d_in[3];
    const float* ad1 = (const float*)d_in[4];
    const float* b1  = (const float*)d_in[5];
    const float* W2  = (const float*)d_in[6];
    const float* as2 = (const float*)d_in[7];
    const float* ad2 = (const float*)d_in[8];
    const float* b2  = (const float*)d_in[9];
    float* out = (float*)d_out;

    // edge_index dtype probe (reads 64 bytes only)
    detect_kernel<<<1, 1>>>(ei);

    // CSR build (same graph for both layers)
    zero_cnt_kernel<<<(NN + 255) / 256, 256>>>();
    deg_kernel<<<(NE + 255) / 256, 256>>>(ei);
    scan_kernel<<<1, 1024>>>();
    scatter_kernel<<<(NE + 255) / 256, 256>>>(ei);
    self_kernel<<<(NN + 255) / 256, 256>>>();

    dim3 gg((NN + 127) / 128, 2);

    // layer 1 (H=8, F=32)
    gemm_kernel<false><<<gg, 256>>>(x, W1, NN);
    al_kernel<8><<<NN, 256>>>(as1, ad1);
    softmax_kernel<8><<<NN, 256>>>();
    agg_kernel<8, true><<<NN, 256>>>(b1, nullptr);

    // layer 2 (H=1, F=256)
    gemm_kernel<true><<<gg, 256>>>(nullptr, W2, NN);
    al_kernel<1><<<NN, 256>>>(as2, ad2);
    softmax_kernel<1><<<NN, 256>>>();
    agg_kernel<1, false><<<NN, 256>>>(b2, out);
}

// round 4
// speedup vs baseline: 1.3855x; 1.3855x over previous
#include <cuda_runtime.h>
#include <cstdint>

#define NN   50000
#define EMBD 256
#define NE   800000
#define ETOT (NE + NN)
#define NBLK 196                      // ceil(NN/256)

// ---------------- static device scratch ----------------
__device__ float g_h[(size_t)NN * EMBD];
__device__ float g_o1[(size_t)NN * EMBD];
__device__ float g_als[NN * 8];
__device__ float g_ald[NN * 8];
__device__ float g_alpha[(size_t)ETOT * 8];
__device__ int   g_rowptr[NN + 1];
__device__ int   g_cnt[NN];
__device__ int   g_srcs[ETOT];
__device__ int   g_tmp[NN];
__device__ int   g_bsum[NBLK];
__device__ int   g_boff[NBLK];
__device__ int   g_is64;

__device__ __forceinline__ float lrelu(float x) { return x > 0.f ? x : 0.2f * x; }

__device__ __forceinline__ int edge_at(const void* ei, long long idx) {
    if (g_is64) return (int)((const long long*)ei)[idx];
    return ((const int*)ei)[idx];
}

__device__ __forceinline__ uint32_t f2tf(float f) {
    uint32_t u;
    asm("cvt.rna.tf32.f32 %0, %1;" : "=r"(u) : "f"(f));
    return u;
}

// ---------------- dtype probe ----------------
__global__ void detect_kernel(const void* ei) {
    const long long* p = (const long long*)ei;
    bool ok = true;
    #pragma unroll
    for (int i = 0; i < 8; i++) {
        long long v = p[i];
        if (v < 0 || v >= NN) ok = false;
    }
    g_is64 = ok ? 1 : 0;
}

// ---------------- CSR build ----------------
__global__ void zero_cnt_kernel() {
    int i = blockIdx.x * blockDim.x + threadIdx.x;
    if (i < NN) g_cnt[i] = 0;
}

__global__ void deg_kernel(const void* __restrict__ ei) {
    int e = blockIdx.x * blockDim.x + threadIdx.x;
    if (e < NE) atomicAdd(&g_cnt[edge_at(ei, (long long)NE + e)], 1);
}

// phase 1: per-block inclusive scan of (cnt+1); write incl to g_tmp, block total to g_bsum
__global__ void __launch_bounds__(256) scan1_kernel() {
    __shared__ int wsum[8];
    const int t = threadIdx.x, b = blockIdx.x;
    const int i = b * 256 + t;
    int v = (i < NN) ? g_cnt[i] + 1 : 0;
    int x = v;
    #pragma unroll
    for (int o = 1; o < 32; o <<= 1) {
        int y = __shfl_up_sync(0xffffffffu, x, o);
        if ((t & 31) >= o) x += y;
    }
    if ((t & 31) == 31) wsum[t >> 5] = x;
    __syncthreads();
    if (t < 8) {
        int w = wsum[t];
        #pragma unroll
        for (int o = 1; o < 8; o <<= 1) {
            int y = __shfl_up_sync(0xffu, w, o);
            if (t >= o) w += y;
        }
        wsum[t] = w;
    }
    __syncthreads();
    int incl = x + ((t >= 32) ? wsum[(t >> 5) - 1] : 0);
    if (i < NN) g_tmp[i] = incl;
    if (t == 255) g_bsum[b] = incl;
}

// phase 2: single-block exclusive scan of the 196 block sums
__global__ void __launch_bounds__(256) scan2_kernel() {
    __shared__ int wsum[8];
    const int t = threadIdx.x;
    int v = (t < NBLK) ? g_bsum[t] : 0;
    int x = v;
    #pragma unroll
    for (int o = 1; o < 32; o <<= 1) {
        int y = __shfl_up_sync(0xffffffffu, x, o);
        if ((t & 31) >= o) x += y;
    }
    if ((t & 31) == 31) wsum[t >> 5] = x;
    __syncthreads();
    if (t < 8) {
        int w = wsum[t];
        #pragma unroll
        for (int o = 1; o < 8; o <<= 1) {
            int y = __shfl_up_sync(0xffu, w, o);
            if (t >= o) w += y;
        }
        wsum[t] = w;
    }
    __syncthreads();
    int incl = x + ((t >= 32) ? wsum[(t >> 5) - 1] : 0);
    if (t < NBLK) g_boff[t] = incl - v;
    if (t == 0) g_rowptr[0] = 0;
}

// phase 3: add offsets -> rowptr; zero cnt (scatter cursor)
__global__ void scan3_kernel() {
    int i = blockIdx.x * blockDim.x + threadIdx.x;
    if (i < NN) {
        g_rowptr[i + 1] = g_tmp[i] + g_boff[i >> 8];
        g_cnt[i] = 0;
    }
}

__global__ void scatter_kernel(const void* __restrict__ ei) {
    int e = blockIdx.x * blockDim.x + threadIdx.x;
    if (e < NE) {
        int s = edge_at(ei, e);
        int d = edge_at(ei, (long long)NE + e);
        int pos = g_rowptr[d] + atomicAdd(&g_cnt[d], 1);
        g_srcs[pos] = s;
    }
}

__global__ void self_kernel() {
    int i = blockIdx.x * blockDim.x + threadIdx.x;
    if (i < NN) g_srcs[g_rowptr[i + 1] - 1] = i;
}

// ---------------- tf32 tensor-core GEMM: g_h[M,256] = A[M,256] @ B[256,256] ----------------
// 128x128 block tile, K chunks of 32, 8 warps of 32x64, mma.m16n8k8.tf32.
template <bool INTERNAL_SRC>
__global__ void __launch_bounds__(256) gemm_tc_kernel(const float* __restrict__ Aext,
                                                      const float* __restrict__ B, int M) {
    const float* A = INTERNAL_SRC ? g_o1 : Aext;
    float* C = g_h;

    __shared__ uint32_t As[32][129];   // [k][m], pad 1 word
    __shared__ uint32_t Bs[32][132];   // [k][n], pad 4 words (16B-aligned rows)

    const int t    = threadIdx.x;
    const int lane = t & 31;
    const int w    = t >> 5;
    const int wr   = w & 3;            // warp row: m offset wr*32
    const int wc   = w >> 2;           // warp col: n offset wc*64
    const int tig  = lane & 3;
    const int gid  = lane >> 2;
    const int bm   = blockIdx.x * 128;
    const int bn   = blockIdx.y * 128;

    float acc[2][8][4];
    #pragma unroll
    for (int mt = 0; mt < 2; mt++)
        #pragma unroll
        for (int nt = 0; nt < 8; nt++)
            #pragma unroll
            for (int c = 0; c < 4; c++) acc[mt][nt][c] = 0.f;

    const int a_r   = t >> 3;          // 0..31 (base row within tile, step 32)
    const int a_ko  = (t & 7) * 4;     // local k offset 0..28
    const int b_row = t >> 3;          // reuse pattern for B? no: below

    for (int kc = 0; kc < 8; kc++) {
        const int kbase = kc * 32;
        // load A chunk: 128 rows x 32 k -> transposed to As[k][m]
        #pragma unroll
        for (int i = 0; i < 4; i++) {
            int r = a_r + i * 32;               // 0..127
            int grow = bm + r;
            float4 v = (grow < M) ? *(const float4*)(A + (size_t)grow * EMBD + kbase + a_ko)
                                  : make_float4(0.f, 0.f, 0.f, 0.f);
            As[a_ko + 0][r] = f2tf(v.x);
            As[a_ko + 1][r] = f2tf(v.y);
            As[a_ko + 2][r] = f2tf(v.z);
            As[a_ko + 3][r] = f2tf(v.w);
        }
        // load B chunk: 32 k-rows x 128 n -> Bs[k][n]
        #pragma unroll
        for (int i = 0; i < 4; i++) {
            int idx  = t + i * 256;             // 0..1023
            int kr   = idx >> 5;                // 0..31
            int c4   = (idx & 31) * 4;          // 0..124
            float4 v = *(const float4*)(B + (size_t)(kbase + kr) * EMBD + bn + c4);
            uint4 u;
            u.x = f2tf(v.x); u.y = f2tf(v.y); u.z = f2tf(v.z); u.w = f2tf(v.w);
            *(uint4*)&Bs[kr][c4] = u;
        }
        __syncthreads();

        #pragma unroll
        for (int k0 = 0; k0 < 32; k0 += 8) {
            uint32_t af[2][4], bf[8][2];
            const int kr0 = k0 + tig, kr1 = k0 + tig + 4;
            #pragma unroll
            for (int mt = 0; mt < 2; mt++) {
                int m0 = wr * 32 + mt * 16 + gid;
                af[mt][0] = As[kr0][m0];
                af[mt][1] = As[kr0][m0 + 8];
                af[mt][2] = As[kr1][m0];
                af[mt][3] = As[kr1][m0 + 8];
            }
            #pragma unroll
            for (int nt = 0; nt < 8; nt++) {
                int n0 = wc * 64 + nt * 8 + gid;
                bf[nt][0] = Bs[kr0][n0];
                bf[nt][1] = Bs[kr1][n0];
            }
            #pragma unroll
            for (int mt = 0; mt < 2; mt++)
                #pragma unroll
                for (int nt = 0; nt < 8; nt++) {
                    asm volatile(
                        "mma.sync.aligned.m16n8k8.row.col.f32.tf32.tf32.f32 "
                        "{%0,%1,%2,%3}, {%4,%5,%6,%7}, {%8,%9}, {%0,%1,%2,%3};\n"
                        : "+f"(acc[mt][nt][0]), "+f"(acc[mt][nt][1]),
                          "+f"(acc[mt][nt][2]), "+f"(acc[mt][nt][3])
                        : "r"(af[mt][0]), "r"(af[mt][1]), "r"(af[mt][2]), "r"(af[mt][3]),
                          "r"(bf[nt][0]), "r"(bf[nt][1]));
                }
        }
        __syncthreads();
    }

    // epilogue
    #pragma unroll
    for (int mt = 0; mt < 2; mt++) {
        int row0 = bm + wr * 32 + mt * 16 + gid;
        #pragma unroll
        for (int nt = 0; nt < 8; nt++) {
            int col = bn + wc * 64 + nt * 8 + tig * 2;
            if (row0 < M)
                *(float2*)(C + (size_t)row0 * EMBD + col) = make_float2(acc[mt][nt][0], acc[mt][nt][1]);
            if (row0 + 8 < M)
                *(float2*)(C + (size_t)(row0 + 8) * EMBD + col) = make_float2(acc[mt][nt][2], acc[mt][nt][3]);
        }
    }
}

// ---------------- per-node attention logits ----------------
template <int H>
__global__ void al_kernel(const float* __restrict__ asrc,
                          const float* __restrict__ adst) {
    int n = blockIdx.x, t = threadIdx.x;
    float v  = g_h[(size_t)n * EMBD + t];
    float ps = v * asrc[t];
    float pd = v * adst[t];
    #pragma unroll
    for (int o = 16; o; o >>= 1) {
        ps += __shfl_xor_sync(0xffffffffu, ps, o);
        pd += __shfl_xor_sync(0xffffffffu, pd, o);
    }
    if (H == 8) {
        if ((t & 31) == 0) { g_als[n * 8 + (t >> 5)] = ps; g_ald[n * 8 + (t >> 5)] = pd; }
    } else {
        __shared__ float sps[8], spd[8];
        if ((t & 31) == 0) { sps[t >> 5] = ps; spd[t >> 5] = pd; }
        __syncthreads();
        if (t == 0) {
            float a = 0.f, b = 0.f;
            #pragma unroll
            for (int ww = 0; ww < 8; ww++) { a += sps[ww]; b += spd[ww]; }
            g_als[n] = a; g_ald[n] = b;
        }
    }
}

// ---------------- segment softmax ----------------
template <int H>
__global__ void __launch_bounds__(256) softmax_kernel() {
    constexpr int CAP   = (H == 8) ? 512 : 4096;
    constexpr int GROUP = (H == 8) ? 32 : 256;
    __shared__ float lsh[H][CAP];
    __shared__ float red[8];

    const int d = blockIdx.x;
    const int begin = g_rowptr[d], end = g_rowptr[d + 1];
    const int deg = end - begin;
    const int hh   = (H == 8) ? (threadIdx.x >> 5) : 0;
    const int lane = (H == 8) ? (threadIdx.x & 31) : threadIdx.x;
    const float aldv = g_ald[d * H + hh];

    float m = -1e30f;
    for (int i = lane; i < deg; i += GROUP) {
        int s = g_srcs[begin + i];
        float lg = lrelu(g_als[s * H + hh] + aldv);
        if (i < CAP) lsh[hh][i] = lg;
        m = fmaxf(m, lg);
    }
    #pragma unroll
    for (int o = 16; o; o >>= 1) m = fmaxf(m, __shfl_xor_sync(0xffffffffu, m, o));
    if (H == 1) {
        if ((threadIdx.x & 31) == 0) red[threadIdx.x >> 5] = m;
        __syncthreads();
        m = red[0];
        #pragma unroll
        for (int ww = 1; ww < 8; ww++) m = fmaxf(m, red[ww]);
        __syncthreads();
    }

    float z = 0.f;
    for (int i = lane; i < deg; i += GROUP) {
        float lg = (i < CAP) ? lsh[hh][i]
                             : lrelu(g_als[g_srcs[begin + i] * H + hh] + aldv);
        z += __expf(lg - m);
    }
    #pragma unroll
    for (int o = 16; o; o >>= 1) z += __shfl_xor_sync(0xffffffffu, z, o);
    if (H == 1) {
        if ((threadIdx.x & 31) == 0) red[threadIdx.x >> 5] = z;
        __syncthreads();
        z = 0.f;
        #pragma unroll
        for (int ww = 0; ww < 8; ww++) z += red[ww];
    }

    const float inv = 1.f / (z + 1e-16f);
    for (int i = lane; i < deg; i += GROUP) {
        float lg = (i < CAP) ? lsh[hh][i]
                             : lrelu(g_als[g_srcs[begin + i] * H + hh] + aldv);
        g_alpha[(size_t)(begin + i) * H + hh] = __expf(lg - m) * inv;
    }
}

// ---------------- aggregation ----------------
template <int H, bool INTERNAL_DST>
__global__ void __launch_bounds__(256) agg_kernel(const float* __restrict__ bias,
                                                  float* __restrict__ outext) {
    constexpr int F = EMBD / H;
    const int d = blockIdx.x, t = threadIdx.x;
    const int hh = t / F;
    const int begin = g_rowptr[d], end = g_rowptr[d + 1];

    __shared__ int   s_src[64];
    __shared__ float s_alpha[64 * H];

    float acc = 0.f;
    for (int c = begin; c < end; c += 64) {
        int len = min(64, end - c);
        __syncthreads();
        if (t < len) s_src[t] = g_srcs[c + t];
        for (int i = t; i < len * H; i += 256) s_alpha[i] = g_alpha[(size_t)c * H + i];
        __syncthreads();
        #pragma unroll 4
        for (int j = 0; j < len; j++)
            acc += s_alpha[j * H + hh] * g_h[(size_t)s_src[j] * EMBD + t];
    }
    float r = acc + bias[t];
    if (INTERNAL_DST) g_o1[(size_t)d * EMBD + t] = r;
    else              outext[(size_t)d * EMBD + t] = r;
}

// ---------------- launch ----------------
extern "C" void kernel_launch(void* const* d_in, const int* in_sizes, int n_in,
                              void* d_out, int out_size) {
    const float* x   = (const float*)d_in[0];
    const void*  ei  = d_in[1];
    const float* W1  = (const float*)d_in[2];
    const float* as1 = (const float*)d_in[3];
    const float* ad1 = (const float*)d_in[4];
    const float* b1  = (const float*)d_in[5];
    const float* W2  = (const float*)d_in[6];
    const float* as2 = (const float*)d_in[7];
    const float* ad2 = (const float*)d_in[8];
    const float* b2  = (const float*)d_in[9];
    float* out = (float*)d_out;

    detect_kernel<<<1, 1>>>(ei);

    zero_cnt_kernel<<<NBLK, 256>>>();
    deg_kernel<<<(NE + 255) / 256, 256>>>(ei);
    scan1_kernel<<<NBLK, 256>>>();
    scan2_kernel<<<1, 256>>>();
    scan3_kernel<<<NBLK, 256>>>();
    scatter_kernel<<<(NE + 255) / 256, 256>>>(ei);
    self_kernel<<<NBLK, 256>>>();

    dim3 gg((NN + 127) / 128, 2);

    // layer 1 (H=8, F=32)
    gemm_tc_kernel<false><<<gg, 256>>>(x, W1, NN);
    al_kernel<8><<<NN, 256>>>(as1, ad1);
    softmax_kernel<8><<<NN, 256>>>();
    agg_kernel<8, true><<<NN, 256>>>(b1, nullptr);

    // layer 2 (H=1, F=256)
    gemm_tc_kernel<true><<<gg, 256>>>(nullptr, W2, NN);
    al_kernel<1><<<NN, 256>>>(as2, ad2);
    softmax_kernel<1><<<NN, 256>>>();
    agg_kernel<1, false><<<NN, 256>>>(b2, out);
}